// round 4
// baseline (speedup 1.0000x reference)
#include <cuda_runtime.h>

#define BSEG 16
#define DF   128
#define DC   256
#define ROWS_PER_BLOCK 512
#define THREADS 256

// Accumulators (scratch) — __device__ globals per the no-allocation rule.
__device__ float g_acc_c[BSEG * DC];
__device__ float g_acc_f[BSEG * DF];

__global__ void zero_acc_kernel() {
    int i = blockIdx.x * blockDim.x + threadIdx.x;
    if (i < BSEG * DC) g_acc_c[i] = 0.0f;
    if (i < BSEG * DF) g_acc_f[i] = 0.0f;
}

// COLS4: number of float4 per row (32 for D=128, 64 for D=256).
// ROWLANES = THREADS / COLS4 rows processed per iteration.
template <int COLS4, int ROWLANES>
__device__ __forceinline__ void reduce_tile(const float4* __restrict__ feats,
                                            const int*    __restrict__ lengths,
                                            float*        __restrict__ acc,
                                            int n_rows, int tile_id)
{
    __shared__ int    cum[BSEG + 1];
    __shared__ float4 sh[ROWLANES][COLS4];

    const int tid = threadIdx.x;
    if (tid == 0) {
        int c = 0;
        cum[0] = 0;
        #pragma unroll
        for (int b = 0; b < BSEG; b++) { c += lengths[b]; cum[b + 1] = c; }
    }
    __syncthreads();

    const int row0    = tile_id * ROWS_PER_BLOCK;
    const int row_end = min(row0 + ROWS_PER_BLOCK, n_rows);
    if (row0 >= row_end) return;

    const int col4 = tid % COLS4;   // consecutive threads -> consecutive float4: coalesced
    const int rl   = tid / COLS4;

    // Segment containing row0 (linear scan over 16 entries).
    int seg = 0;
    while (cum[seg + 1] <= row0) seg++;

    int row = row0;
    while (row < row_end) {
        const int run_end = min(row_end, cum[seg + 1]);

        // Per-thread register accumulation over this segment-run.
        float4 a = make_float4(0.f, 0.f, 0.f, 0.f);
        #pragma unroll 4
        for (int r = row + rl; r < run_end; r += ROWLANES) {
            float4 v = feats[(long long)r * COLS4 + col4];
            a.x += v.x; a.y += v.y; a.z += v.z; a.w += v.w;
        }

        // Cross-rowlane reduction in shared, then ONE atomic flush per run.
        sh[rl][col4] = a;
        __syncthreads();
        if (rl == 0) {
            float4 s = sh[0][col4];
            #pragma unroll
            for (int k = 1; k < ROWLANES; k++) {
                float4 v = sh[k][col4];
                s.x += v.x; s.y += v.y; s.z += v.z; s.w += v.w;
            }
            float* dst = acc + seg * (COLS4 * 4) + col4 * 4;
            atomicAdd(dst + 0, s.x);
            atomicAdd(dst + 1, s.y);
            atomicAdd(dst + 2, s.z);
            atomicAdd(dst + 3, s.w);
        }
        __syncthreads();  // protect sh[] reuse on next run

        row = run_end;
        seg++;
    }
}

__global__ void reduce_kernel(const float* __restrict__ feats_f,
                              const float* __restrict__ feats_c,
                              const int*   __restrict__ lengths_f,
                              const int*   __restrict__ lengths_c,
                              int nbf, int n_f, int n_c)
{
    if ((int)blockIdx.x < nbf) {
        reduce_tile<DF / 4, THREADS / (DF / 4)>(
            (const float4*)feats_f, lengths_f, g_acc_f, n_f, blockIdx.x);
    } else {
        reduce_tile<DC / 4, THREADS / (DC / 4)>(
            (const float4*)feats_c, lengths_c, g_acc_c, n_c, blockIdx.x - nbf);
    }
}

__global__ void finalize_kernel(float* __restrict__ out,
                                const int* __restrict__ lengths_f,
                                const int* __restrict__ lengths_c)
{
    int i = blockIdx.x * blockDim.x + threadIdx.x;
    const int DTOT = DC + DF;
    if (i >= BSEG * DTOT) return;
    int b = i / DTOT;
    int j = i % DTOT;
    float v;
    if (j < DC) v = g_acc_c[b * DC + j]        / (float)lengths_c[b];
    else        v = g_acc_f[b * DF + (j - DC)] / (float)lengths_f[b];
    out[i] = v;
}

extern "C" void kernel_launch(void* const* d_in, const int* in_sizes, int n_in,
                              void* d_out, int out_size)
{
    const float* feats_f   = (const float*)d_in[0];
    const float* feats_c   = (const float*)d_in[1];
    const int*   lengths_f = (const int*)  d_in[2];
    const int*   lengths_c = (const int*)  d_in[3];
    float*       out       = (float*)d_out;

    const int n_f = in_sizes[0] / DF;   // 524288
    const int n_c = in_sizes[1] / DC;   // 32768

    const int nbf = (n_f + ROWS_PER_BLOCK - 1) / ROWS_PER_BLOCK;  // 1024
    const int nbc = (n_c + ROWS_PER_BLOCK - 1) / ROWS_PER_BLOCK;  // 64

    zero_acc_kernel<<<(BSEG * DC + THREADS - 1) / THREADS, THREADS>>>();
    reduce_kernel<<<nbf + nbc, THREADS>>>(feats_f, feats_c, lengths_f, lengths_c,
                                          nbf, n_f, n_c);
    finalize_kernel<<<(BSEG * (DC + DF) + THREADS - 1) / THREADS, THREADS>>>(
        out, lengths_f, lengths_c);
}

// round 5
// speedup vs baseline: 1.1170x; 1.1170x over previous
#include <cuda_runtime.h>

#define BSEG 16
#define DF   128
#define DC   256
#define THREADS 256
#define NBF 526          // fine blocks   (256 MB / 526  ≈ 498 KB/block)
#define NBC 66           // coarse blocks ( 32 MB / 66   ≈ 497 KB/block)
#define GRID (NBF + NBC) // 592 = 148 SMs * 4 blocks

// Scratch: __device__ globals (no allocation). Zero-initialized at load;
// the last block re-zeroes them each call, so every call is self-restoring.
__device__ float    g_acc_c[BSEG * DC];
__device__ float    g_acc_f[BSEG * DF];
__device__ unsigned g_done;

// COLS4 = float4 per row (32 for D=128, 64 for D=256); ROWLANES = THREADS/COLS4.
template <int COLS4>
__device__ __forceinline__ void reduce_range(const float4* __restrict__ feats,
                                             const int* __restrict__ cum,
                                             float* __restrict__ acc,
                                             int row0, int row_end,
                                             float4* __restrict__ sh)
{
    constexpr int ROWLANES = THREADS / COLS4;
    const int tid  = threadIdx.x;
    const int col4 = tid % COLS4;   // consecutive threads -> consecutive float4 (coalesced)
    const int rl   = tid / COLS4;

    // Segment containing row0 (<=16 shared loads).
    int seg = 0;
    while (cum[seg + 1] <= row0) seg++;

    int row = row0;
    while (row < row_end) {
        const int run_end = min(row_end, cum[seg + 1]);

        // Per-thread register accumulation over this segment-run.
        float4 a = make_float4(0.f, 0.f, 0.f, 0.f);
        #pragma unroll 8
        for (int r = row + rl; r < run_end; r += ROWLANES) {
            float4 v = __ldcs(feats + r * COLS4 + col4);   // streaming, read-once
            a.x += v.x; a.y += v.y; a.z += v.z; a.w += v.w;
        }

        // Cross-rowlane reduction in shared, one atomic flush per (block, run).
        sh[rl * COLS4 + col4] = a;
        __syncthreads();
        if (rl == 0) {
            float4 s = sh[col4];
            #pragma unroll
            for (int k = 1; k < ROWLANES; k++) {
                float4 v = sh[k * COLS4 + col4];
                s.x += v.x; s.y += v.y; s.z += v.z; s.w += v.w;
            }
            float* dst = acc + seg * (COLS4 * 4) + col4 * 4;
            atomicAdd(dst + 0, s.x);
            atomicAdd(dst + 1, s.y);
            atomicAdd(dst + 2, s.z);
            atomicAdd(dst + 3, s.w);
        }
        __syncthreads();   // protect sh[] reuse on the next run

        row = run_end;
        seg++;
    }
}

__global__ void __launch_bounds__(THREADS, 4)
fused_segmean_kernel(const float4* __restrict__ feats_f,
                     const float4* __restrict__ feats_c,
                     const int*    __restrict__ lengths_f,
                     const int*    __restrict__ lengths_c,
                     float*        __restrict__ out,
                     int n_f, int n_c)
{
    __shared__ int    cum_f[BSEG + 1];
    __shared__ int    cum_c[BSEG + 1];
    __shared__ float4 sh[THREADS];
    __shared__ bool   is_last;

    const int tid = threadIdx.x;
    if (tid == 0) {
        int c = 0; cum_f[0] = 0;
        #pragma unroll
        for (int b = 0; b < BSEG; b++) { c += lengths_f[b]; cum_f[b + 1] = c; }
    } else if (tid == 32) {
        int c = 0; cum_c[0] = 0;
        #pragma unroll
        for (int b = 0; b < BSEG; b++) { c += lengths_c[b]; cum_c[b + 1] = c; }
    }
    __syncthreads();

    // Static, byte-balanced row partition: every block owns ~498 KB.
    const int bid = blockIdx.x;
    if (bid < NBF) {
        int r0 = (int)((long long)bid       * n_f / NBF);
        int r1 = (int)((long long)(bid + 1) * n_f / NBF);
        reduce_range<DF / 4>(feats_f, cum_f, g_acc_f, r0, r1, sh);
    } else {
        int cb = bid - NBF;
        int r0 = (int)((long long)cb       * n_c / NBC);
        int r1 = (int)((long long)(cb + 1) * n_c / NBC);
        reduce_range<DC / 4>(feats_c, cum_c, g_acc_c, r0, r1, sh);
    }

    // ---- last-block finalize (replaces separate zero + finalize launches) ----
    __threadfence();                      // make this block's atomics L2-visible
    __syncthreads();
    if (tid == 0) is_last = (atomicAdd(&g_done, 1u) == GRID - 1);
    __syncthreads();
    if (!is_last) return;

    const int DTOT = DC + DF;
    for (int i = tid; i < BSEG * DTOT; i += THREADS) {
        int b = i / DTOT, j = i % DTOT;
        float v, inv;
        if (j < DC) {
            v   = __ldcg(&g_acc_c[b * DC + j]);
            inv = 1.0f / (float)(cum_c[b + 1] - cum_c[b]);
        } else {
            v   = __ldcg(&g_acc_f[b * DF + (j - DC)]);
            inv = 1.0f / (float)(cum_f[b + 1] - cum_f[b]);
        }
        out[i] = v * inv;
    }

    // Restore state for the next graph replay.
    for (int i = tid; i < BSEG * DC; i += THREADS) g_acc_c[i] = 0.f;
    for (int i = tid; i < BSEG * DF; i += THREADS) g_acc_f[i] = 0.f;
    if (tid == 0) g_done = 0u;
}

extern "C" void kernel_launch(void* const* d_in, const int* in_sizes, int n_in,
                              void* d_out, int out_size)
{
    const float4* feats_f   = (const float4*)d_in[0];
    const float4* feats_c   = (const float4*)d_in[1];
    const int*    lengths_f = (const int*)   d_in[2];
    const int*    lengths_c = (const int*)   d_in[3];
    float*        out       = (float*)d_out;

    const int n_f = in_sizes[0] / DF;   // 524288
    const int n_c = in_sizes[1] / DC;   // 32768

    fused_segmean_kernel<<<GRID, THREADS>>>(feats_f, feats_c,
                                            lengths_f, lengths_c,
                                            out, n_f, n_c);
}